// round 1
// baseline (speedup 1.0000x reference)
#include <cuda_runtime.h>
#include <cuda_bf16.h>

// Problem constants
#define BSZ   2
#define LSEQ  1024
#define DMODEL 1024
#define NH    16
#define DH    64
#define WWIN  64
#define MTOT  (BSZ * LSEQ)   // 2048

// Scratch (device globals — no allocation allowed)
__device__ float g_q[MTOT * DMODEL];
__device__ float g_k[MTOT * DMODEL];
__device__ float g_v[MTOT * DMODEL];
__device__ float g_att[MTOT * DMODEL];

// ---------------------------------------------------------------------------
// GEMM: C = A (M x K) @ W(N x K)^T   with M=2048, N=1024, K=1024 hardcoded.
// 128x128 block tile, BK=16, 256 threads, 8x8 per thread.
// blockIdx.z selects among up to 3 (W, C) pairs (used to fuse Q/K/V).
// ---------------------------------------------------------------------------
__global__ __launch_bounds__(256) void gemm_nt_kernel(
    const float* __restrict__ A,
    const float* __restrict__ W0, const float* __restrict__ W1, const float* __restrict__ W2,
    float* __restrict__ C0, float* __restrict__ C1, float* __restrict__ C2)
{
    const float* Wm = (blockIdx.z == 0) ? W0 : ((blockIdx.z == 1) ? W1 : W2);
    float*       Cm = (blockIdx.z == 0) ? C0 : ((blockIdx.z == 1) ? C1 : C2);

    const int bn = blockIdx.x * 128;
    const int bm = blockIdx.y * 128;

    __shared__ float As[16][132];   // [k][m], padded
    __shared__ float Bs[16][132];   // [k][n], padded

    const int tid = threadIdx.x;
    const int tx = tid & 15;        // 0..15  (n direction)
    const int ty = tid >> 4;        // 0..15  (m direction)

    // loading indices: each thread loads 2 float4 from A and 2 from W
    const int lr = tid >> 2;          // 0..63
    const int lc = (tid & 3) * 4;     // 0,4,8,12

    const float* Aptr = A  + (size_t)(bm + lr) * DMODEL + lc;
    const float* Wptr = Wm + (size_t)(bn + lr) * DMODEL + lc;

    float acc[8][8];
    #pragma unroll
    for (int i = 0; i < 8; i++)
        #pragma unroll
        for (int j = 0; j < 8; j++) acc[i][j] = 0.0f;

    for (int k0 = 0; k0 < DMODEL; k0 += 16) {
        float4 a0 = *(const float4*)(Aptr + k0);
        float4 a1 = *(const float4*)(Aptr + (size_t)64 * DMODEL + k0);
        float4 b0 = *(const float4*)(Wptr + k0);
        float4 b1 = *(const float4*)(Wptr + (size_t)64 * DMODEL + k0);

        As[lc + 0][lr]      = a0.x; As[lc + 1][lr]      = a0.y;
        As[lc + 2][lr]      = a0.z; As[lc + 3][lr]      = a0.w;
        As[lc + 0][lr + 64] = a1.x; As[lc + 1][lr + 64] = a1.y;
        As[lc + 2][lr + 64] = a1.z; As[lc + 3][lr + 64] = a1.w;

        Bs[lc + 0][lr]      = b0.x; Bs[lc + 1][lr]      = b0.y;
        Bs[lc + 2][lr]      = b0.z; Bs[lc + 3][lr]      = b0.w;
        Bs[lc + 0][lr + 64] = b1.x; Bs[lc + 1][lr + 64] = b1.y;
        Bs[lc + 2][lr + 64] = b1.z; Bs[lc + 3][lr + 64] = b1.w;

        __syncthreads();

        #pragma unroll
        for (int kk = 0; kk < 16; kk++) {
            float ar[8], br[8];
            #pragma unroll
            for (int i = 0; i < 8; i++) ar[i] = As[kk][ty * 8 + i];
            #pragma unroll
            for (int j = 0; j < 8; j++) br[j] = Bs[kk][tx * 8 + j];
            #pragma unroll
            for (int i = 0; i < 8; i++)
                #pragma unroll
                for (int j = 0; j < 8; j++)
                    acc[i][j] += ar[i] * br[j];
        }
        __syncthreads();
    }

    #pragma unroll
    for (int i = 0; i < 8; i++) {
        float* crow = Cm + (size_t)(bm + ty * 8 + i) * DMODEL + bn + tx * 8;
        float4 v0 = make_float4(acc[i][0], acc[i][1], acc[i][2], acc[i][3]);
        float4 v1 = make_float4(acc[i][4], acc[i][5], acc[i][6], acc[i][7]);
        *(float4*)(crow)     = v0;
        *(float4*)(crow + 4) = v1;
    }
}

// ---------------------------------------------------------------------------
// Band attention: one block = (64 queries) x (1 head) x (1 batch).
// Window for query l covers padded positions [l, l+W-1] where
// padded = concat(last_init[0..W-2], seq[0..L-1]).
// smem: K window 127x64, V window 127x64, Q 64x64, scores 64x64.
// ---------------------------------------------------------------------------
#define KV_STRIDE 68   // row pad (float4-aligned, avoids bank conflicts)
#define S_STRIDE  66

__global__ __launch_bounds__(256) void band_attn_kernel(
    const float* __restrict__ last_k, const float* __restrict__ last_v)
{
    extern __shared__ float smem[];
    float* sK = smem;                     // 127 * 68
    float* sV = sK + 127 * KV_STRIDE;     // 127 * 68
    float* sQ = sV + 127 * KV_STRIDE;     // 64 * 68
    float* sS = sQ + 64 * KV_STRIDE;      // 64 * 66

    const int l0 = blockIdx.x * 64;
    const int h  = blockIdx.y;
    const int b  = blockIdx.z;
    const int tid = threadIdx.x;

    // --- load Q (64 rows x 64 cols, float4) ---
    for (int idx = tid; idx < 64 * 16; idx += 256) {
        int r = idx >> 4, c4 = (idx & 15) * 4;
        float4 v = *(const float4*)(g_q + (size_t)(b * LSEQ + l0 + r) * DMODEL + h * DH + c4);
        *(float4*)(sQ + r * KV_STRIDE + c4) = v;
    }
    // --- load K/V window (127 padded rows x 64 cols, float4) ---
    for (int idx = tid; idx < 127 * 16; idx += 256) {
        int r = idx >> 4, c4 = (idx & 15) * 4;
        int p = l0 + r;  // padded index
        const float *ks, *vs;
        if (p < WWIN - 1) {
            ks = last_k + (size_t)(p * NH + h) * DH + c4;
            vs = last_v + (size_t)(p * NH + h) * DH + c4;
        } else {
            int pos = p - (WWIN - 1);
            ks = g_k + (size_t)(b * LSEQ + pos) * DMODEL + h * DH + c4;
            vs = g_v + (size_t)(b * LSEQ + pos) * DMODEL + h * DH + c4;
        }
        *(float4*)(sK + r * KV_STRIDE + c4) = *(const float4*)ks;
        *(float4*)(sV + r * KV_STRIDE + c4) = *(const float4*)vs;
    }
    __syncthreads();

    const int q   = tid >> 2;   // 0..63
    const int sub = tid & 3;    // 0..3

    // cache this thread's Q row in registers
    float qreg[64];
    #pragma unroll
    for (int c4 = 0; c4 < 64; c4 += 4) {
        float4 v = *(const float4*)(sQ + q * KV_STRIDE + c4);
        qreg[c4 + 0] = v.x; qreg[c4 + 1] = v.y; qreg[c4 + 2] = v.z; qreg[c4 + 3] = v.w;
    }

    // --- scores: thread handles w = sub, sub+4, ..., sub+60 ---
    #pragma unroll 4
    for (int i = 0; i < 16; i++) {
        int w = sub + i * 4;
        const float* kr = sK + (q + w) * KV_STRIDE;
        float acc = 0.0f;
        #pragma unroll
        for (int c4 = 0; c4 < 64; c4 += 4) {
            float4 kv = *(const float4*)(kr + c4);
            acc += qreg[c4 + 0] * kv.x + qreg[c4 + 1] * kv.y
                 + qreg[c4 + 2] * kv.z + qreg[c4 + 3] * kv.w;
        }
        sS[q * S_STRIDE + w] = acc * 0.125f;  // dh^-0.5 = 1/8
    }
    __syncthreads();

    // --- softmax over w (one thread per query) ---
    if (tid < 64) {
        float* row = sS + tid * S_STRIDE;
        float m = row[0];
        #pragma unroll 8
        for (int w = 1; w < 64; w++) m = fmaxf(m, row[w]);
        float s = 0.0f;
        #pragma unroll 8
        for (int w = 0; w < 64; w++) { float e = __expf(row[w] - m); row[w] = e; s += e; }
        float inv = 1.0f / s;
        #pragma unroll 8
        for (int w = 0; w < 64; w++) row[w] *= inv;
    }
    __syncthreads();

    // --- output: thread handles d = sub*16 .. sub*16+15 for its query ---
    float acc[16];
    #pragma unroll
    for (int j = 0; j < 16; j++) acc[j] = 0.0f;

    for (int w = 0; w < 64; w++) {
        float p = sS[q * S_STRIDE + w];
        const float* vr = sV + (q + w) * KV_STRIDE + sub * 16;
        #pragma unroll
        for (int c4 = 0; c4 < 16; c4 += 4) {
            float4 vv = *(const float4*)(vr + c4);
            acc[c4 + 0] += p * vv.x; acc[c4 + 1] += p * vv.y;
            acc[c4 + 2] += p * vv.z; acc[c4 + 3] += p * vv.w;
        }
    }

    float* outp = g_att + (size_t)(b * LSEQ + l0 + q) * DMODEL + h * DH + sub * 16;
    #pragma unroll
    for (int c4 = 0; c4 < 16; c4 += 4)
        *(float4*)(outp + c4) = make_float4(acc[c4], acc[c4+1], acc[c4+2], acc[c4+3]);
}

// ---------------------------------------------------------------------------
// Launch
// ---------------------------------------------------------------------------
extern "C" void kernel_launch(void* const* d_in, const int* in_sizes, int n_in,
                              void* d_out, int out_size)
{
    const float* x      = (const float*)d_in[0];
    const float* Wq     = (const float*)d_in[1];
    const float* Wk     = (const float*)d_in[2];
    const float* Wv     = (const float*)d_in[3];
    const float* Wo     = (const float*)d_in[4];
    const float* last_k = (const float*)d_in[5];
    const float* last_v = (const float*)d_in[6];
    float* out = (float*)d_out;

    float *pq, *pk, *pv, *patt;
    cudaGetSymbolAddress((void**)&pq,   g_q);
    cudaGetSymbolAddress((void**)&pk,   g_k);
    cudaGetSymbolAddress((void**)&pv,   g_v);
    cudaGetSymbolAddress((void**)&patt, g_att);

    // attention smem size
    const int attn_smem = (127 * KV_STRIDE * 2 + 64 * KV_STRIDE + 64 * S_STRIDE) * (int)sizeof(float);
    cudaFuncSetAttribute(band_attn_kernel, cudaFuncAttributeMaxDynamicSharedMemorySize, attn_smem);

    // 1) fused QKV projections: q/k/v = x @ W{q,k,v}^T
    dim3 gQKV(DMODEL / 128, MTOT / 128, 3);
    gemm_nt_kernel<<<gQKV, 256>>>(x, Wq, Wk, Wv, pq, pk, pv);

    // 2) band attention
    dim3 gAtt(LSEQ / 64, NH, BSZ);
    band_attn_kernel<<<gAtt, 256, attn_smem>>>(last_k, last_v);

    // 3) output projection: out = att @ Wo^T
    dim3 gOut(DMODEL / 128, MTOT / 128, 1);
    gemm_nt_kernel<<<gOut, 256>>>(patt, Wo, Wo, Wo, out, out, out);
}

// round 3
// speedup vs baseline: 2.6582x; 2.6582x over previous
#include <cuda_runtime.h>
#include <cuda_bf16.h>
#include <cstdint>

// Problem constants
#define BSZ    2
#define LSEQ   1024
#define DMODEL 1024
#define NH     16
#define DH     64
#define WWIN   64
#define MTOT   (BSZ * LSEQ)      // 2048

// ---------------------------------------------------------------------------
// Scratch (device globals — no allocation allowed)
// ---------------------------------------------------------------------------
__device__ float g_xr  [MTOT * DMODEL];         // x rounded to tf32
__device__ float g_wr  [3 * DMODEL * DMODEL];   // Wq|Wk|Wv rows stacked, tf32-rounded
__device__ float g_wor [DMODEL * DMODEL];       // Wo tf32-rounded
__device__ float g_attr[MTOT * DMODEL];         // attention out, tf32-rounded
__device__ float g_qkv [MTOT * 3 * DMODEL];     // q|k|v f32, row-concat
__device__ float g_att [MTOT * DMODEL];         // attention out f32

// ---------------------------------------------------------------------------
// helpers
// ---------------------------------------------------------------------------
__device__ __forceinline__ uint32_t smem_u32(const void* p) {
    uint32_t a;
    asm("{ .reg .u64 t; cvta.to.shared.u64 t, %1; cvt.u32.u64 %0, t; }" : "=r"(a) : "l"(p));
    return a;
}
__device__ __forceinline__ float tf32_round(float v) {
    uint32_t o;
    asm("cvt.rna.tf32.f32 %0, %1;" : "=r"(o) : "f"(v));
    return __uint_as_float(o);
}
#define CP_ASYNC16(dst, src) \
    asm volatile("cp.async.cg.shared.global [%0], [%1], 16;" :: "r"(dst), "l"(src) : "memory")
#define CP_ASYNC_COMMIT() asm volatile("cp.async.commit_group;" ::: "memory")
#define CP_ASYNC_WAIT(n)  asm volatile("cp.async.wait_group %0;" :: "n"(n) : "memory")

__device__ __forceinline__ void mma_tf32(float* c, uint32_t a0, uint32_t a1,
                                         uint32_t a2, uint32_t a3,
                                         uint32_t b0, uint32_t b1) {
    asm volatile(
        "mma.sync.aligned.m16n8k8.row.col.f32.tf32.tf32.f32 "
        "{%0,%1,%2,%3}, {%4,%5,%6,%7}, {%8,%9}, {%0,%1,%2,%3};"
        : "+f"(c[0]), "+f"(c[1]), "+f"(c[2]), "+f"(c[3])
        : "r"(a0), "r"(a1), "r"(a2), "r"(a3), "r"(b0), "r"(b1));
}

// ---------------------------------------------------------------------------
// TF32 tensor-core GEMM: C[M][Ntot] = A[M][1024] @ B[Ntot][1024]^T
// CTA 128x128, BK=32, 4 warps (64x64 warp tiles), cp.async double buffer.
// smem rows padded to 36 words -> fragment LDS bank-conflict-free.
// ---------------------------------------------------------------------------
#define BK 32
#define SROW 36                       // padded row, words
#define TILE_WORDS (128 * SROW)       // 4608 words per matrix per stage
#define STAGE_WORDS (2 * TILE_WORDS)  // A + B
#define GEMM_SMEM_BYTES (2 * STAGE_WORDS * 4)  // 73728

__global__ __launch_bounds__(128, 1) void gemm_tf32_kernel(
    const float* __restrict__ A, const float* __restrict__ B,
    float* __restrict__ C, int Ntot)
{
    extern __shared__ float smem[];
    const int tid  = threadIdx.x;
    const int wid  = tid >> 5;
    const int lane = tid & 31;
    const int bn = blockIdx.x * 128;
    const int bm = blockIdx.y * 128;

    const int wm = (wid & 1) * 64;   // warp m offset in tile
    const int wn = (wid >> 1) * 64;  // warp n offset in tile

    const int qr = lane >> 2;        // 0..7
    const int qc = lane & 3;         // 0..3

    const uint32_t smem_base = smem_u32(smem);

    const float* gA = A + (size_t)bm * DMODEL;
    const float* gB = B + (size_t)bn * DMODEL;

    // stage loader: 1024 16B chunks each for A and B; 8 each per thread
    auto load_stage = [&](int s) {
        const int buf = s & 1;
        uint32_t dstA = smem_base + (uint32_t)buf * (STAGE_WORDS * 4);
        uint32_t dstB = dstA + TILE_WORDS * 4;
        const float* pA = gA + s * BK;
        const float* pB = gB + s * BK;
        #pragma unroll
        for (int i = 0; i < 8; i++) {
            int id = tid + i * 128;       // 0..1023
            int row = id >> 3;            // 0..127
            int ch  = id & 7;             // 16B chunk in 128B of real data
            uint32_t so = (uint32_t)(row * SROW + ch * 4) * 4;
            CP_ASYNC16(dstA + so, pA + (size_t)row * DMODEL + ch * 4);
            CP_ASYNC16(dstB + so, pB + (size_t)row * DMODEL + ch * 4);
        }
    };

    float acc[4][8][4];
    #pragma unroll
    for (int mi = 0; mi < 4; mi++)
        #pragma unroll
        for (int ni = 0; ni < 8; ni++)
            #pragma unroll
            for (int j = 0; j < 4; j++) acc[mi][ni][j] = 0.0f;

    const int NSTAGE = DMODEL / BK;  // 32
    load_stage(0); CP_ASYNC_COMMIT();

    for (int s = 0; s < NSTAGE; s++) {
        if (s + 1 < NSTAGE) {
            load_stage(s + 1); CP_ASYNC_COMMIT();
            CP_ASYNC_WAIT(1);
        } else {
            CP_ASYNC_WAIT(0);
        }
        __syncthreads();

        const float* sA = smem + (s & 1) * STAGE_WORDS;
        const float* sB = sA + TILE_WORDS;

        #pragma unroll
        for (int ks = 0; ks < 4; ks++) {
            const int k0 = ks * 8;
            uint32_t af[4][4];
            #pragma unroll
            for (int mi = 0; mi < 4; mi++) {
                const float* base = sA + (wm + mi * 16 + qr) * SROW + k0 + qc;
                af[mi][0] = __float_as_uint(base[0]);
                af[mi][1] = __float_as_uint(base[8 * SROW]);
                af[mi][2] = __float_as_uint(base[4]);
                af[mi][3] = __float_as_uint(base[8 * SROW + 4]);
            }
            uint32_t bf[8][2];
            #pragma unroll
            for (int ni = 0; ni < 8; ni++) {
                const float* base = sB + (wn + ni * 8 + qr) * SROW + k0 + qc;
                bf[ni][0] = __float_as_uint(base[0]);
                bf[ni][1] = __float_as_uint(base[4]);
            }
            #pragma unroll
            for (int mi = 0; mi < 4; mi++)
                #pragma unroll
                for (int ni = 0; ni < 8; ni++)
                    mma_tf32(acc[mi][ni], af[mi][0], af[mi][1], af[mi][2], af[mi][3],
                             bf[ni][0], bf[ni][1]);
        }
        __syncthreads();
    }

    // epilogue: direct global stores (float2 per half-fragment)
    #pragma unroll
    for (int mi = 0; mi < 4; mi++) {
        const int row = bm + wm + mi * 16 + qr;
        #pragma unroll
        for (int ni = 0; ni < 8; ni++) {
            const int col = bn + wn + ni * 8 + qc * 2;
            float* p0 = C + (size_t)row * Ntot + col;
            float* p1 = p0 + (size_t)8 * Ntot;
            *(float2*)p0 = make_float2(acc[mi][ni][0], acc[mi][ni][1]);
            *(float2*)p1 = make_float2(acc[mi][ni][2], acc[mi][ni][3]);
        }
    }
}

// ---------------------------------------------------------------------------
// tf32 rounding prepasses
// ---------------------------------------------------------------------------
__global__ __launch_bounds__(256) void round_kernel(
    const float* __restrict__ src, float* __restrict__ dst, int n4)
{
    int i = blockIdx.x * 256 + threadIdx.x;
    if (i >= n4) return;
    float4 v = ((const float4*)src)[i];
    v.x = tf32_round(v.x); v.y = tf32_round(v.y);
    v.z = tf32_round(v.z); v.w = tf32_round(v.w);
    ((float4*)dst)[i] = v;
}

__global__ __launch_bounds__(256) void round_w3_kernel(
    const float* __restrict__ Wq, const float* __restrict__ Wk,
    const float* __restrict__ Wv, float* __restrict__ dst)
{
    int i = blockIdx.x * 256 + threadIdx.x;          // over 3M/4 float4s
    int n4 = 3 * DMODEL * DMODEL / 4;
    if (i >= n4) return;
    int seg = i / (DMODEL * DMODEL / 4);
    int off = i - seg * (DMODEL * DMODEL / 4);
    const float* W = (seg == 0) ? Wq : ((seg == 1) ? Wk : Wv);
    float4 v = ((const float4*)W)[off];
    v.x = tf32_round(v.x); v.y = tf32_round(v.y);
    v.z = tf32_round(v.z); v.w = tf32_round(v.w);
    ((float4*)dst)[i] = v;
}

// ---------------------------------------------------------------------------
// Band attention (fp32). Reads q|k|v from g_qkv [2048][3072]; writes g_att.
// ---------------------------------------------------------------------------
#define KV_STRIDE 68
#define S_STRIDE  66
#define QKV_LD    (3 * DMODEL)

__global__ __launch_bounds__(256) void band_attn_kernel(
    const float* __restrict__ last_k, const float* __restrict__ last_v)
{
    extern __shared__ float smem[];
    float* sK = smem;
    float* sV = sK + 127 * KV_STRIDE;
    float* sQ = sV + 127 * KV_STRIDE;
    float* sS = sQ + 64 * KV_STRIDE;

    const int l0 = blockIdx.x * 64;
    const int h  = blockIdx.y;
    const int b  = blockIdx.z;
    const int tid = threadIdx.x;

    for (int idx = tid; idx < 64 * 16; idx += 256) {
        int r = idx >> 4, c4 = (idx & 15) * 4;
        float4 v = *(const float4*)(g_qkv + (size_t)(b * LSEQ + l0 + r) * QKV_LD + h * DH + c4);
        *(float4*)(sQ + r * KV_STRIDE + c4) = v;
    }
    for (int idx = tid; idx < 127 * 16; idx += 256) {
        int r = idx >> 4, c4 = (idx & 15) * 4;
        int p = l0 + r;
        const float *ks, *vs;
        if (p < WWIN - 1) {
            ks = last_k + (size_t)(p * NH + h) * DH + c4;
            vs = last_v + (size_t)(p * NH + h) * DH + c4;
        } else {
            int pos = p - (WWIN - 1);
            const float* base = g_qkv + (size_t)(b * LSEQ + pos) * QKV_LD + h * DH + c4;
            ks = base + DMODEL;
            vs = base + 2 * DMODEL;
        }
        *(float4*)(sK + r * KV_STRIDE + c4) = *(const float4*)ks;
        *(float4*)(sV + r * KV_STRIDE + c4) = *(const float4*)vs;
    }
    __syncthreads();

    const int q   = tid >> 2;
    const int sub = tid & 3;

    float qreg[64];
    #pragma unroll
    for (int c4 = 0; c4 < 64; c4 += 4) {
        float4 v = *(const float4*)(sQ + q * KV_STRIDE + c4);
        qreg[c4 + 0] = v.x; qreg[c4 + 1] = v.y; qreg[c4 + 2] = v.z; qreg[c4 + 3] = v.w;
    }

    #pragma unroll 4
    for (int i = 0; i < 16; i++) {
        int w = sub + i * 4;
        const float* kr = sK + (q + w) * KV_STRIDE;
        float acc = 0.0f;
        #pragma unroll
        for (int c4 = 0; c4 < 64; c4 += 4) {
            float4 kv = *(const float4*)(kr + c4);
            acc += qreg[c4 + 0] * kv.x + qreg[c4 + 1] * kv.y
                 + qreg[c4 + 2] * kv.z + qreg[c4 + 3] * kv.w;
        }
        sS[q * S_STRIDE + w] = acc * 0.125f;
    }
    __syncthreads();

    if (tid < 64) {
        float* row = sS + tid * S_STRIDE;
        float m = row[0];
        #pragma unroll 8
        for (int w = 1; w < 64; w++) m = fmaxf(m, row[w]);
        float s = 0.0f;
        #pragma unroll 8
        for (int w = 0; w < 64; w++) { float e = __expf(row[w] - m); row[w] = e; s += e; }
        float inv = 1.0f / s;
        #pragma unroll 8
        for (int w = 0; w < 64; w++) row[w] *= inv;
    }
    __syncthreads();

    float acc[16];
    #pragma unroll
    for (int j = 0; j < 16; j++) acc[j] = 0.0f;

    for (int w = 0; w < 64; w++) {
        float p = sS[q * S_STRIDE + w];
        const float* vr = sV + (q + w) * KV_STRIDE + sub * 16;
        #pragma unroll
        for (int c4 = 0; c4 < 16; c4 += 4) {
            float4 vv = *(const float4*)(vr + c4);
            acc[c4 + 0] += p * vv.x; acc[c4 + 1] += p * vv.y;
            acc[c4 + 2] += p * vv.z; acc[c4 + 3] += p * vv.w;
        }
    }

    float* outp = g_att + (size_t)(b * LSEQ + l0 + q) * DMODEL + h * DH + sub * 16;
    #pragma unroll
    for (int c4 = 0; c4 < 16; c4 += 4)
        *(float4*)(outp + c4) = make_float4(acc[c4], acc[c4+1], acc[c4+2], acc[c4+3]);
}

// ---------------------------------------------------------------------------
// Launch
// ---------------------------------------------------------------------------
extern "C" void kernel_launch(void* const* d_in, const int* in_sizes, int n_in,
                              void* d_out, int out_size)
{
    const float* x      = (const float*)d_in[0];
    const float* Wq     = (const float*)d_in[1];
    const float* Wk     = (const float*)d_in[2];
    const float* Wv     = (const float*)d_in[3];
    const float* Wo     = (const float*)d_in[4];
    const float* last_k = (const float*)d_in[5];
    const float* last_v = (const float*)d_in[6];
    float* out = (float*)d_out;

    float *pxr, *pwr, *pwor, *pattr, *pqkv, *patt;
    cudaGetSymbolAddress((void**)&pxr,   g_xr);
    cudaGetSymbolAddress((void**)&pwr,   g_wr);
    cudaGetSymbolAddress((void**)&pwor,  g_wor);
    cudaGetSymbolAddress((void**)&pattr, g_attr);
    cudaGetSymbolAddress((void**)&pqkv,  g_qkv);
    cudaGetSymbolAddress((void**)&patt,  g_att);

    cudaFuncSetAttribute(gemm_tf32_kernel, cudaFuncAttributeMaxDynamicSharedMemorySize,
                         GEMM_SMEM_BYTES);
    const int attn_smem = (127 * KV_STRIDE * 2 + 64 * KV_STRIDE + 64 * S_STRIDE) * (int)sizeof(float);
    cudaFuncSetAttribute(band_attn_kernel, cudaFuncAttributeMaxDynamicSharedMemorySize, attn_smem);

    // 1) tf32-round inputs
    round_kernel<<<(MTOT * DMODEL / 4 + 255) / 256, 256>>>(x, pxr, MTOT * DMODEL / 4);
    round_w3_kernel<<<(3 * DMODEL * DMODEL / 4 + 255) / 256, 256>>>(Wq, Wk, Wv, pwr);
    round_kernel<<<(DMODEL * DMODEL / 4 + 255) / 256, 256>>>(Wo, pwor, DMODEL * DMODEL / 4);

    // 2) fused QKV: g_qkv[2048][3072] = xr @ wr^T
    {
        dim3 g(3 * DMODEL / 128, MTOT / 128);
        gemm_tf32_kernel<<<g, 128, GEMM_SMEM_BYTES>>>(pxr, pwr, pqkv, 3 * DMODEL);
    }

    // 3) band attention -> g_att
    {
        dim3 g(LSEQ / 64, NH, BSZ);
        band_attn_kernel<<<g, 256, attn_smem>>>(last_k, last_v);
    }

    // 4) round attention output
    round_kernel<<<(MTOT * DMODEL / 4 + 255) / 256, 256>>>(patt, pattr, MTOT * DMODEL / 4);

    // 5) out = attr @ wor^T
    {
        dim3 g(DMODEL / 128, MTOT / 128);
        gemm_tf32_kernel<<<g, 128, GEMM_SMEM_BYTES>>>(pattr, pwor, out, DMODEL);
    }
}

// round 5
// speedup vs baseline: 2.7213x; 1.0237x over previous
#include <cuda_runtime.h>
#include <cuda_bf16.h>
#include <cstdint>

// Problem constants
#define BSZ    2
#define LSEQ   1024
#define DMODEL 1024
#define NH     16
#define DH     64
#define WWIN   64
#define MTOT   (BSZ * LSEQ)      // 2048

// ---------------------------------------------------------------------------
// Scratch (device globals — no allocation allowed)
// ---------------------------------------------------------------------------
__device__ float g_xr  [MTOT * DMODEL];         // x rounded to tf32
__device__ float g_wr  [3 * DMODEL * DMODEL];   // Wq|Wk|Wv rows stacked, tf32-rounded
__device__ float g_wor [DMODEL * DMODEL];       // Wo tf32-rounded
__device__ float g_attr[MTOT * DMODEL];         // attention out, tf32-rounded
__device__ float g_qkv [MTOT * 3 * DMODEL];     // q|k|v f32, row-concat

// ---------------------------------------------------------------------------
// helpers
// ---------------------------------------------------------------------------
__device__ __forceinline__ uint32_t smem_u32(const void* p) {
    uint32_t a;
    asm("{ .reg .u64 t; cvta.to.shared.u64 t, %1; cvt.u32.u64 %0, t; }" : "=r"(a) : "l"(p));
    return a;
}
__device__ __forceinline__ float tf32_round(float v) {
    uint32_t o;
    asm("cvt.rna.tf32.f32 %0, %1;" : "=r"(o) : "f"(v));
    return __uint_as_float(o);
}
#define CP_ASYNC16(dst, src) \
    asm volatile("cp.async.cg.shared.global [%0], [%1], 16;" :: "r"(dst), "l"(src) : "memory")
#define CP_ASYNC_COMMIT() asm volatile("cp.async.commit_group;" ::: "memory")
#define CP_ASYNC_WAIT(n)  asm volatile("cp.async.wait_group %0;" :: "n"(n) : "memory")

__device__ __forceinline__ void mma_tf32(float* c, uint32_t a0, uint32_t a1,
                                         uint32_t a2, uint32_t a3,
                                         uint32_t b0, uint32_t b1) {
    asm volatile(
        "mma.sync.aligned.m16n8k8.row.col.f32.tf32.tf32.f32 "
        "{%0,%1,%2,%3}, {%4,%5,%6,%7}, {%8,%9}, {%0,%1,%2,%3};"
        : "+f"(c[0]), "+f"(c[1]), "+f"(c[2]), "+f"(c[3])
        : "r"(a0), "r"(a1), "r"(a2), "r"(a3), "r"(b0), "r"(b1));
}

// ---------------------------------------------------------------------------
// TF32 tensor-core GEMM: C[M][Ntot] = A[M][1024] @ B[Ntot][1024]^T
// CTA 128x128, BK=32, 8 warps (64x32 warp tiles), cp.async double buffer.
// 2 CTAs/SM (regs capped by launch_bounds), smem rows padded to 36 words.
// ---------------------------------------------------------------------------
#define BK 32
#define SROW 36                       // padded row, words
#define TILE_WORDS (128 * SROW)       // 4608 words per matrix per stage
#define STAGE_WORDS (2 * TILE_WORDS)  // A + B
#define GEMM_SMEM_BYTES (2 * STAGE_WORDS * 4)  // 73728

__global__ __launch_bounds__(256, 2) void gemm_tf32_kernel(
    const float* __restrict__ A, const float* __restrict__ B,
    float* __restrict__ C, int Ntot)
{
    extern __shared__ float smem[];
    const int tid  = threadIdx.x;
    const int wid  = tid >> 5;
    const int lane = tid & 31;
    const int bn = blockIdx.x * 128;
    const int bm = blockIdx.y * 128;

    const int wm = (wid & 1) * 64;    // warp m offset (2 warps over 128 rows)
    const int wn = (wid >> 1) * 32;   // warp n offset (4 warps over 128 cols)

    const int qr = lane >> 2;         // 0..7
    const int qc = lane & 3;          // 0..3

    const uint32_t smem_base = smem_u32(smem);

    const float* gA = A + (size_t)bm * DMODEL;
    const float* gB = B + (size_t)bn * DMODEL;

    // stage loader: 1024 16B chunks each for A and B; 4 each per thread
    auto load_stage = [&](int s) {
        const int buf = s & 1;
        uint32_t dstA = smem_base + (uint32_t)buf * (STAGE_WORDS * 4);
        uint32_t dstB = dstA + TILE_WORDS * 4;
        const float* pA = gA + s * BK;
        const float* pB = gB + s * BK;
        #pragma unroll
        for (int i = 0; i < 4; i++) {
            int id = tid + i * 256;       // 0..1023
            int row = id >> 3;            // 0..127
            int ch  = id & 7;             // 16B chunk in 128B of real data
            uint32_t so = (uint32_t)(row * SROW + ch * 4) * 4;
            CP_ASYNC16(dstA + so, pA + (size_t)row * DMODEL + ch * 4);
            CP_ASYNC16(dstB + so, pB + (size_t)row * DMODEL + ch * 4);
        }
    };

    float acc[4][4][4];
    #pragma unroll
    for (int mi = 0; mi < 4; mi++)
        #pragma unroll
        for (int ni = 0; ni < 4; ni++)
            #pragma unroll
            for (int j = 0; j < 4; j++) acc[mi][ni][j] = 0.0f;

    const int NSTAGE = DMODEL / BK;  // 32
    load_stage(0); CP_ASYNC_COMMIT();

    for (int s = 0; s < NSTAGE; s++) {
        if (s + 1 < NSTAGE) {
            load_stage(s + 1); CP_ASYNC_COMMIT();
            CP_ASYNC_WAIT(1);
        } else {
            CP_ASYNC_WAIT(0);
        }
        __syncthreads();

        const float* sA = smem + (s & 1) * STAGE_WORDS;
        const float* sB = sA + TILE_WORDS;

        #pragma unroll
        for (int ks = 0; ks < 4; ks++) {
            const int k0 = ks * 8;
            uint32_t af[4][4];
            #pragma unroll
            for (int mi = 0; mi < 4; mi++) {
                const float* base = sA + (wm + mi * 16 + qr) * SROW + k0 + qc;
                af[mi][0] = __float_as_uint(base[0]);
                af[mi][1] = __float_as_uint(base[8 * SROW]);
                af[mi][2] = __float_as_uint(base[4]);
                af[mi][3] = __float_as_uint(base[8 * SROW + 4]);
            }
            uint32_t bf[4][2];
            #pragma unroll
            for (int ni = 0; ni < 4; ni++) {
                const float* base = sB + (wn + ni * 8 + qr) * SROW + k0 + qc;
                bf[ni][0] = __float_as_uint(base[0]);
                bf[ni][1] = __float_as_uint(base[4]);
            }
            #pragma unroll
            for (int mi = 0; mi < 4; mi++)
                #pragma unroll
                for (int ni = 0; ni < 4; ni++)
                    mma_tf32(acc[mi][ni], af[mi][0], af[mi][1], af[mi][2], af[mi][3],
                             bf[ni][0], bf[ni][1]);
        }
        __syncthreads();
    }

    // epilogue: direct global stores
    #pragma unroll
    for (int mi = 0; mi < 4; mi++) {
        const int row = bm + wm + mi * 16 + qr;
        #pragma unroll
        for (int ni = 0; ni < 4; ni++) {
            const int col = bn + wn + ni * 8 + qc * 2;
            float* p0 = C + (size_t)row * Ntot + col;
            float* p1 = p0 + (size_t)8 * Ntot;
            *(float2*)p0 = make_float2(acc[mi][ni][0], acc[mi][ni][1]);
            *(float2*)p1 = make_float2(acc[mi][ni][2], acc[mi][ni][3]);
        }
    }
}

// ---------------------------------------------------------------------------
// tf32 rounding prepasses
// ---------------------------------------------------------------------------
__global__ __launch_bounds__(256) void round_kernel(
    const float* __restrict__ src, float* __restrict__ dst, int n4)
{
    int i = blockIdx.x * 256 + threadIdx.x;
    if (i >= n4) return;
    float4 v = ((const float4*)src)[i];
    v.x = tf32_round(v.x); v.y = tf32_round(v.y);
    v.z = tf32_round(v.z); v.w = tf32_round(v.w);
    ((float4*)dst)[i] = v;
}

__global__ __launch_bounds__(256) void round_w3_kernel(
    const float* __restrict__ Wq, const float* __restrict__ Wk,
    const float* __restrict__ Wv, float* __restrict__ dst)
{
    int i = blockIdx.x * 256 + threadIdx.x;
    int n4 = 3 * DMODEL * DMODEL / 4;
    if (i >= n4) return;
    int seg = i / (DMODEL * DMODEL / 4);
    int off = i - seg * (DMODEL * DMODEL / 4);
    const float* W = (seg == 0) ? Wq : ((seg == 1) ? Wk : Wv);
    float4 v = ((const float4*)W)[off];
    v.x = tf32_round(v.x); v.y = tf32_round(v.y);
    v.z = tf32_round(v.z); v.w = tf32_round(v.w);
    ((float4*)dst)[i] = v;
}

// ---------------------------------------------------------------------------
// Band attention (fp32 math, shuffle softmax). Reads q|k|v from g_qkv;
// writes tf32-rounded output directly to g_attr (out-proj input).
// ---------------------------------------------------------------------------
#define KV_STRIDE 68
#define S_STRIDE  66
#define QKV_LD    (3 * DMODEL)

__global__ __launch_bounds__(256) void band_attn_kernel(
    const float* __restrict__ last_k, const float* __restrict__ last_v)
{
    extern __shared__ float smem[];
    float* sK = smem;
    float* sV = sK + 127 * KV_STRIDE;
    float* sQ = sV + 127 * KV_STRIDE;
    float* sS = sQ + 64 * KV_STRIDE;

    const int l0 = blockIdx.x * 64;
    const int h  = blockIdx.y;
    const int b  = blockIdx.z;
    const int tid = threadIdx.x;

    for (int idx = tid; idx < 64 * 16; idx += 256) {
        int r = idx >> 4, c4 = (idx & 15) * 4;
        float4 v = *(const float4*)(g_qkv + (size_t)(b * LSEQ + l0 + r) * QKV_LD + h * DH + c4);
        *(float4*)(sQ + r * KV_STRIDE + c4) = v;
    }
    for (int idx = tid; idx < 127 * 16; idx += 256) {
        int r = idx >> 4, c4 = (idx & 15) * 4;
        int p = l0 + r;
        const float *ks, *vs;
        if (p < WWIN - 1) {
            ks = last_k + (size_t)(p * NH + h) * DH + c4;
            vs = last_v + (size_t)(p * NH + h) * DH + c4;
        } else {
            int pos = p - (WWIN - 1);
            const float* base = g_qkv + (size_t)(b * LSEQ + pos) * QKV_LD + h * DH + c4;
            ks = base + DMODEL;
            vs = base + 2 * DMODEL;
        }
        *(float4*)(sK + r * KV_STRIDE + c4) = *(const float4*)ks;
        *(float4*)(sV + r * KV_STRIDE + c4) = *(const float4*)vs;
    }
    __syncthreads();

    const int q   = tid >> 2;
    const int sub = tid & 3;

    float qreg[64];
    #pragma unroll
    for (int c4 = 0; c4 < 64; c4 += 4) {
        float4 v = *(const float4*)(sQ + q * KV_STRIDE + c4);
        qreg[c4 + 0] = v.x; qreg[c4 + 1] = v.y; qreg[c4 + 2] = v.z; qreg[c4 + 3] = v.w;
    }

    // scores in registers: thread covers w = sub, sub+4, ..., sub+60
    float sreg[16];
    #pragma unroll 4
    for (int i = 0; i < 16; i++) {
        int w = sub + i * 4;
        const float* kr = sK + (q + w) * KV_STRIDE;
        float acc = 0.0f;
        #pragma unroll
        for (int c4 = 0; c4 < 64; c4 += 4) {
            float4 kv = *(const float4*)(kr + c4);
            acc += qreg[c4 + 0] * kv.x + qreg[c4 + 1] * kv.y
                 + qreg[c4 + 2] * kv.z + qreg[c4 + 3] * kv.w;
        }
        sreg[i] = acc * 0.125f;
    }

    // quad-shuffle softmax (lanes 4q..4q+3 hold the 64 scores of query q)
    float m = sreg[0];
    #pragma unroll
    for (int i = 1; i < 16; i++) m = fmaxf(m, sreg[i]);
    m = fmaxf(m, __shfl_xor_sync(0xFFFFFFFFu, m, 1));
    m = fmaxf(m, __shfl_xor_sync(0xFFFFFFFFu, m, 2));
    float ssum = 0.0f;
    #pragma unroll
    for (int i = 0; i < 16; i++) { float e = __expf(sreg[i] - m); sreg[i] = e; ssum += e; }
    ssum += __shfl_xor_sync(0xFFFFFFFFu, ssum, 1);
    ssum += __shfl_xor_sync(0xFFFFFFFFu, ssum, 2);
    const float inv = 1.0f / ssum;
    #pragma unroll
    for (int i = 0; i < 16; i++) sS[q * S_STRIDE + sub + i * 4] = sreg[i] * inv;
    __syncthreads();

    // output: thread handles dims [sub*16, sub*16+16) for its query
    float acc[16];
    #pragma unroll
    for (int j = 0; j < 16; j++) acc[j] = 0.0f;

    for (int w = 0; w < 64; w++) {
        float p = sS[q * S_STRIDE + w];
        const float* vr = sV + (q + w) * KV_STRIDE + sub * 16;
        #pragma unroll
        for (int c4 = 0; c4 < 16; c4 += 4) {
            float4 vv = *(const float4*)(vr + c4);
            acc[c4 + 0] += p * vv.x; acc[c4 + 1] += p * vv.y;
            acc[c4 + 2] += p * vv.z; acc[c4 + 3] += p * vv.w;
        }
    }

    // store tf32-rounded (feeds the out-projection GEMM directly)
    float* outp = g_attr + (size_t)(b * LSEQ + l0 + q) * DMODEL + h * DH + sub * 16;
    #pragma unroll
    for (int c4 = 0; c4 < 16; c4 += 4)
        *(float4*)(outp + c4) = make_float4(tf32_round(acc[c4]),     tf32_round(acc[c4 + 1]),
                                            tf32_round(acc[c4 + 2]), tf32_round(acc[c4 + 3]));
}

// ---------------------------------------------------------------------------
// Launch
// ---------------------------------------------------------------------------
extern "C" void kernel_launch(void* const* d_in, const int* in_sizes, int n_in,
                              void* d_out, int out_size)
{
    const float* x      = (const float*)d_in[0];
    const float* Wq     = (const float*)d_in[1];
    const float* Wk     = (const float*)d_in[2];
    const float* Wv     = (const float*)d_in[3];
    const float* Wo     = (const float*)d_in[4];
    const float* last_k = (const float*)d_in[5];
    const float* last_v = (const float*)d_in[6];
    float* out = (float*)d_out;

    float *pxr, *pwr, *pwor, *pattr, *pqkv;
    cudaGetSymbolAddress((void**)&pxr,   g_xr);
    cudaGetSymbolAddress((void**)&pwr,   g_wr);
    cudaGetSymbolAddress((void**)&pwor,  g_wor);
    cudaGetSymbolAddress((void**)&pattr, g_attr);
    cudaGetSymbolAddress((void**)&pqkv,  g_qkv);

    cudaFuncSetAttribute(gemm_tf32_kernel, cudaFuncAttributeMaxDynamicSharedMemorySize,
                         GEMM_SMEM_BYTES);
    const int attn_smem = (127 * KV_STRIDE * 2 + 64 * KV_STRIDE + 64 * S_STRIDE) * (int)sizeof(float);
    cudaFuncSetAttribute(band_attn_kernel, cudaFuncAttributeMaxDynamicSharedMemorySize, attn_smem);

    // 1) tf32-round inputs
    round_kernel<<<(MTOT * DMODEL / 4 + 255) / 256, 256>>>(x, pxr, MTOT * DMODEL / 4);
    round_w3_kernel<<<(3 * DMODEL * DMODEL / 4 + 255) / 256, 256>>>(Wq, Wk, Wv, pwr);
    round_kernel<<<(DMODEL * DMODEL / 4 + 255) / 256, 256>>>(Wo, pwor, DMODEL * DMODEL / 4);

    // 2) fused QKV: g_qkv[2048][3072] = xr @ wr^T
    {
        dim3 g(3 * DMODEL / 128, MTOT / 128);
        gemm_tf32_kernel<<<g, 256, GEMM_SMEM_BYTES>>>(pxr, pwr, pqkv, 3 * DMODEL);
    }

    // 3) band attention -> g_attr (tf32-rounded in epilogue)
    {
        dim3 g(LSEQ / 64, NH, BSZ);
        band_attn_kernel<<<g, 256, attn_smem>>>(last_k, last_v);
    }

    // 4) out = attr @ wor^T
    {
        dim3 g(DMODEL / 128, MTOT / 128);
        gemm_tf32_kernel<<<g, 256, GEMM_SMEM_BYTES>>>(pattr, pwor, out, DMODEL);
    }
}